// round 14
// baseline (speedup 1.0000x reference)
#include <cuda_runtime.h>
#include <cuda_bf16.h>
#include <math.h>
#include <cstdint>

#define D_DIM   768
#define R_DIM   64
#define E_NUM   4
#define NT      1029
#define BATCH   64
#define M_ROWS  (BATCH * NT)        /* 65856 = 64*1029 */

/* scratch: "full" buffer, transposed expert weights, pre-split packed Wu */
__device__ float    g_h[(size_t)M_ROWS * R_DIM];
__device__ float    g_WeT[E_NUM * R_DIM * R_DIM];
__device__ unsigned g_WuP[D_DIM * 64];   /* [d][64w]: hi words 0-31, lo 32-63 */

__device__ __forceinline__ float gelu_exact(float v) {
    return 0.5f * v * (1.0f + erff(v * 0.70710678118654752f));
}

/* bf16 split+pack via packed cvt: two floats -> hi word + lo (residual) word. */
__device__ __forceinline__ void bfsplit2(float f0, float f1,
                                         unsigned& hw, unsigned& lw) {
    asm("cvt.rn.satfinite.bf16x2.f32 %0, %1, %2;" : "=r"(hw) : "f"(f1), "f"(f0));
    float h0 = __uint_as_float(hw << 16);
    float h1 = __uint_as_float(hw & 0xFFFF0000u);
    float r0 = f0 - h0;
    float r1 = f1 - h1;
    asm("cvt.rn.satfinite.bf16x2.f32 %0, %1, %2;" : "=r"(lw) : "f"(r1), "f"(r0));
}

#define MMA_BF16(C, A, B)                                                     \
    asm volatile(                                                             \
        "mma.sync.aligned.m16n8k16.row.col.f32.bf16.bf16.f32 "                \
        "{%0,%1,%2,%3}, {%4,%5,%6,%7}, {%8,%9}, {%0,%1,%2,%3};"               \
        : "+f"((C)[0]), "+f"((C)[1]), "+f"((C)[2]), "+f"((C)[3])              \
        : "r"((A)[0]), "r"((A)[1]), "r"((A)[2]), "r"((A)[3]),                 \
          "r"((B)[0]), "r"((B)[1]))

__device__ __forceinline__ void cp16(void* smem, const void* g) {
    unsigned sa = (unsigned)__cvta_generic_to_shared(smem);
    asm volatile("cp.async.ca.shared.global [%0], [%1], 16;" :: "r"(sa), "l"(g));
}
#define CP_COMMIT() asm volatile("cp.async.commit_group;")
#define CP_WAIT1()  asm volatile("cp.async.wait_group 1;")
#define CP_WAIT0()  asm volatile("cp.async.wait_group 0;")

/* ------------------------------------------------------------------ */
/* K0 merged prep:                                                     */
/*  part 1 (i < 16384): WeT[e][r][s] = We[e][s][r]                     */
/*  part 2: Wu[d][64]*gamma[d] fp32 -> g_WuP[d][64w] packed bf16 hi/lo */
__global__ void k0_prep(const float* __restrict__ We,
                        const float* __restrict__ Wu,
                        const float* __restrict__ gamma) {
    int i = blockIdx.x * 256 + threadIdx.x;
    if (i < E_NUM * R_DIM * R_DIM) {
        int e = i >> 12;
        int r = (i >> 6) & 63;
        int s = i & 63;
        g_WeT[i] = We[(e << 12) + (s << 6) + r];
    }
    int j = i - E_NUM * R_DIM * R_DIM;
    if (j >= 0 && j < D_DIM * 8) {
        int d = j >> 3;
        int g = j & 7;
        float gm = gamma[d];
        const float* src = Wu + d * 64 + g * 8;
        float4 v0 = *(const float4*)(src);
        float4 v1 = *(const float4*)(src + 4);
        unsigned h0,l0,h1,l1,h2,l2,h3,l3;
        bfsplit2(v0.x * gm, v0.y * gm, h0, l0);
        bfsplit2(v0.z * gm, v0.w * gm, h1, l1);
        bfsplit2(v1.x * gm, v1.y * gm, h2, l2);
        bfsplit2(v1.z * gm, v1.w * gm, h3, l3);
        unsigned* dst = g_WuP + d * 64;
        *(uint4*)(dst + g * 4)      = make_uint4(h0, h1, h2, h3);
        *(uint4*)(dst + 32 + g * 4) = make_uint4(l0, l1, l2, l3);
    }
}

/* ------------------------------------------------------------------ */
/* K1 fused (3-term bf16): h = gelu(X.Wd^T) + top-1 MoE -> g_h.        */
/* 128(M)x64(N), K-step 32. Depth-1 LDG prefetch, fast packed convert. */
/* occupancy 3 CTAs/SM (regs capped at ~85; smem 3x48KB = 144KB OK).   */
#define HS 66
__global__ __launch_bounds__(256, 3) void k1_fused(
    const float* __restrict__ X, const float* __restrict__ Wd,
    const float* __restrict__ Wg, const float* __restrict__ be)
{
    __shared__ __align__(16) unsigned s_buf[12288];  /* 48 KB */
    unsigned* Xp0 = s_buf;            /* 128 rows x 32 words */
    unsigned* Xp1 = s_buf + 4096;
    unsigned* Wp0 = s_buf + 8192;     /* 64 rows x 32 words  */
    unsigned* Wp1 = s_buf + 10240;
    float*    Hs  = (float*)s_buf;    /* reuse post-GEMM: 128*66 */

    const int tid  = threadIdx.x;
    const int wid  = tid >> 5;
    const int lane = tid & 31;
    const int wm   = wid >> 1;
    const int wn   = wid & 1;
    const int r4   = lane >> 2;
    const int c4   = lane & 3;
    const int m0   = blockIdx.x * 128;

    /* LDG assignments */
    int xrow[4], xkq[4];
    const float* xptr[4];
#pragma unroll
    for (int j = 0; j < 4; j++) {
        int f = tid + 256 * j;
        xrow[j] = f >> 3; xkq[j] = f & 7;
        int gr = m0 + xrow[j]; if (gr >= M_ROWS) gr = M_ROWS - 1;
        xptr[j] = X + (size_t)gr * D_DIM + xkq[j] * 4;
    }
    int wrow[2], wkq[2];
    const float* wptr[2];
#pragma unroll
    for (int j = 0; j < 2; j++) {
        int f = tid + 256 * j;
        wrow[j] = f >> 3; wkq[j] = f & 7;
        wptr[j] = Wd + wrow[j] * D_DIM + wkq[j] * 4;
    }

    /* fragment base indices */
    int arow[4], bbi[4];
#pragma unroll
    for (int i = 0; i < 4; i++)
        arow[i] = (wm * 32 + r4 + i * 8) * 32 + c4;
#pragma unroll
    for (int nt = 0; nt < 4; nt++)
        bbi[nt] = (wn * 32 + nt * 8 + r4) * 32 + c4;

    float acc[2][4][4];
#pragma unroll
    for (int mt = 0; mt < 2; mt++)
#pragma unroll
        for (int nt = 0; nt < 4; nt++)
#pragma unroll
            for (int i = 0; i < 4; i++) acc[mt][nt][i] = 0.0f;

    float4 xv[4], wv[2];
#pragma unroll
    for (int j = 0; j < 4; j++) xv[j] = *(const float4*)(xptr[j]);
#pragma unroll
    for (int j = 0; j < 2; j++) wv[j] = *(const float4*)(wptr[j]);

    for (int it = 0; it < 24; it++) {
        unsigned* Xp = (it & 1) ? Xp1 : Xp0;
        unsigned* Wp = (it & 1) ? Wp1 : Wp0;

        /* convert + packed store (hi granules 0-3, lo granules 4-7) */
#pragma unroll
        for (int j = 0; j < 4; j++) {
            unsigned hw0, lw0, hw1, lw1;
            bfsplit2(xv[j].x, xv[j].y, hw0, lw0);
            bfsplit2(xv[j].z, xv[j].w, hw1, lw1);
            int row = xrow[j], kq = xkq[j];
            int g   = kq >> 1;
            int wo  = (kq & 1) * 2;
            int bh_ = row * 32 + (( g      ^ (row & 7)) << 2) + wo;
            int bl_ = row * 32 + (((g + 4) ^ (row & 7)) << 2) + wo;
            *(uint2*)&Xp[bh_] = make_uint2(hw0, hw1);
            *(uint2*)&Xp[bl_] = make_uint2(lw0, lw1);
        }
#pragma unroll
        for (int j = 0; j < 2; j++) {
            unsigned hw0, lw0, hw1, lw1;
            bfsplit2(wv[j].x, wv[j].y, hw0, lw0);
            bfsplit2(wv[j].z, wv[j].w, hw1, lw1);
            int row = wrow[j], kq = wkq[j];
            int g   = kq >> 1;
            int wo  = (kq & 1) * 2;
            int bh_ = row * 32 + (( g      ^ (row & 7)) << 2) + wo;
            int bl_ = row * 32 + (((g + 4) ^ (row & 7)) << 2) + wo;
            *(uint2*)&Wp[bh_] = make_uint2(hw0, hw1);
            *(uint2*)&Wp[bl_] = make_uint2(lw0, lw1);
        }

        /* prefetch next k-tile into registers */
        if (it < 23) {
            int kt = (it + 1) * 32;
#pragma unroll
            for (int j = 0; j < 4; j++) xv[j] = *(const float4*)(xptr[j] + kt);
#pragma unroll
            for (int j = 0; j < 2; j++) wv[j] = *(const float4*)(wptr[j] + kt);
        }
        __syncthreads();

#pragma unroll
        for (int kk = 0; kk < 2; kk++) {
            const int p0  = ((kk * 2)     ^ r4) << 2;
            const int p1  = ((kk * 2 + 1) ^ r4) << 2;
            const int q0  = ((kk * 2 + 4) ^ r4) << 2;
            const int q1  = ((kk * 2 + 5) ^ r4) << 2;
            unsigned ah[2][4], al[2][4], bh[4][2], bl[4][2];
#pragma unroll
            for (int mt = 0; mt < 2; mt++) {
                ah[mt][0] = Xp[arow[2*mt]   + p0];
                ah[mt][1] = Xp[arow[2*mt+1] + p0];
                ah[mt][2] = Xp[arow[2*mt]   + p1];
                ah[mt][3] = Xp[arow[2*mt+1] + p1];
                al[mt][0] = Xp[arow[2*mt]   + q0];
                al[mt][1] = Xp[arow[2*mt+1] + q0];
                al[mt][2] = Xp[arow[2*mt]   + q1];
                al[mt][3] = Xp[arow[2*mt+1] + q1];
            }
#pragma unroll
            for (int nt = 0; nt < 4; nt++) {
                bh[nt][0] = Wp[bbi[nt] + p0];
                bh[nt][1] = Wp[bbi[nt] + p1];
                bl[nt][0] = Wp[bbi[nt] + q0];
                bl[nt][1] = Wp[bbi[nt] + q1];
            }
#pragma unroll
            for (int mt = 0; mt < 2; mt++)
#pragma unroll
                for (int nt = 0; nt < 4; nt++) {
                    MMA_BF16(acc[mt][nt], al[mt], bh[nt]);
                    MMA_BF16(acc[mt][nt], ah[mt], bl[nt]);
                    MMA_BF16(acc[mt][nt], ah[mt], bh[nt]);
                }
        }
    }
    __syncthreads();   /* all MMA reads done before s_buf reuse as Hs */

    /* ---- epilogue phase 1: gelu -> Hs (smem), stride 66 ---- */
#pragma unroll
    for (int mt = 0; mt < 2; mt++) {
        int lr = wm * 32 + mt * 16 + r4;
#pragma unroll
        for (int nt = 0; nt < 4; nt++) {
            int col = wn * 32 + nt * 8 + 2 * c4;
            Hs[lr * HS + col]           = gelu_exact(acc[mt][nt][0]);
            Hs[lr * HS + col + 1]       = gelu_exact(acc[mt][nt][1]);
            Hs[(lr + 8) * HS + col]     = gelu_exact(acc[mt][nt][2]);
            Hs[(lr + 8) * HS + col + 1] = gelu_exact(acc[mt][nt][3]);
        }
    }
    __syncthreads();

    /* ---- epilogue phase 2: per-token MoE, write final to g_h ---- */
    for (int grp = 0; grp < 4; grp++) {
        const int tb = wid * 16 + grp * 4;

        int   esel[4];
        float wsel[4];
        int   grow[4];
        int   vmoe[4];
#pragma unroll
        for (int j = 0; j < 4; j++) {
            int t = tb + j;
            int gr = m0 + t;
            grow[j] = gr;
            if (gr >= M_ROWS) { vmoe[j] = 0; }
            else {
                int bidx = gr / NT;
                int nidx = gr - bidx * NT;
                vmoe[j] = (nidx >= 5) ? 2 : 1;
            }
            float h0 = Hs[t * HS + lane];
            float h1 = Hs[t * HS + 32 + lane];
            float l0 = h0 * __ldg(Wg + lane)       + h1 * __ldg(Wg + 32 + lane);
            float l1 = h0 * __ldg(Wg + 64 + lane)  + h1 * __ldg(Wg + 96 + lane);
            float l2 = h0 * __ldg(Wg + 128 + lane) + h1 * __ldg(Wg + 160 + lane);
            float l3 = h0 * __ldg(Wg + 192 + lane) + h1 * __ldg(Wg + 224 + lane);
#pragma unroll
            for (int o = 16; o > 0; o >>= 1) {
                l0 += __shfl_xor_sync(0xffffffffu, l0, o);
                l1 += __shfl_xor_sync(0xffffffffu, l1, o);
                l2 += __shfl_xor_sync(0xffffffffu, l2, o);
                l3 += __shfl_xor_sync(0xffffffffu, l3, o);
            }
            float mx = fmaxf(fmaxf(l0, l1), fmaxf(l2, l3));
            float e0 = __expf(l0 - mx);
            float e1 = __expf(l1 - mx);
            float e2 = __expf(l2 - mx);
            float e3 = __expf(l3 - mx);
            float ssum = e0 + e1 + e2 + e3;
            int am = 0; float bv = l0; float ev = e0;
            if (l1 > bv) { bv = l1; am = 1; ev = e1; }
            if (l2 > bv) { bv = l2; am = 2; ev = e2; }
            if (l3 > bv) { bv = l3; am = 3; ev = e3; }
            esel[j] = am;
            wsel[j] = ev / ssum;
        }

        float acc2[4][2];
#pragma unroll
        for (int j = 0; j < 4; j++) { acc2[j][0] = 0.0f; acc2[j][1] = 0.0f; }
        const float* wp[4];
#pragma unroll
        for (int j = 0; j < 4; j++) wp[j] = g_WeT + (esel[j] << 12);

#pragma unroll 8
        for (int r = 0; r < 64; r++) {
#pragma unroll
            for (int j = 0; j < 4; j++) {
                float hr = Hs[(tb + j) * HS + r];
                float2 wv2 = *(const float2*)(wp[j] + (r << 6) + lane * 2);
                acc2[j][0] = fmaf(hr, wv2.x, acc2[j][0]);
                acc2[j][1] = fmaf(hr, wv2.y, acc2[j][1]);
            }
        }

#pragma unroll
        for (int j = 0; j < 4; j++) {
            if (vmoe[j] == 0) continue;
            int t = tb + j;
            int e = esel[j];
            float s = (vmoe[j] == 2) ? wsel[j] : 0.0f;
            float b0 = __ldg(be + (e << 6) + lane * 2);
            float b1 = __ldg(be + (e << 6) + lane * 2 + 1);
            float2 hv;
            hv.x = Hs[t * HS + lane * 2];
            hv.y = Hs[t * HS + lane * 2 + 1];
            float2 o;
            o.x = hv.x + s * (acc2[j][0] + b0);
            o.y = hv.y + s * (acc2[j][1] + b1);
            *(float2*)(g_h + (size_t)grow[j] * R_DIM + lane * 2) = o;
        }
    }
}

/* ------------------------------------------------------------------ */
/* K3 (3-term bf16): out = full . (Wu*gamma)^T   (gamma pre-folded)    */
/* M-tile 64. 8 warps 2m x 4n. A fragments register-resident.          */
__global__ __launch_bounds__(256, 2) void k3_gemm_out(float* __restrict__ out)
{
    __shared__ __align__(16) unsigned As[64 * 64];      /* 16 KB */
    __shared__ __align__(16) unsigned Br[2][64 * 64];   /* 2x16 KB */

    const int tid  = threadIdx.x;
    const int wid  = tid >> 5;
    const int lane = tid & 31;
    const int wm   = wid >> 2;          /* 0..1 */
    const int wn   = wid & 3;           /* 0..3 */
    const int r4   = lane >> 2;
    const int c4   = lane & 3;
    const int m0   = blockIdx.x * 64;

    /* A pack: 64 rows x 64 k fp32 -> packed bf16 hi(w0-31)/lo(w32-63) */
#pragma unroll
    for (int j = 0; j < 4; j++) {
        int f = tid + 256 * j;
        int row = f >> 4, kq = f & 15;
        float4 v = *(const float4*)(g_h + (size_t)(m0 + row) * R_DIM + kq * 4);
        unsigned hw0, lw0, hw1, lw1;
        bfsplit2(v.x, v.y, hw0, lw0);
        bfsplit2(v.z, v.w, hw1, lw1);
        int g  = kq >> 1;
        int wo = (kq & 1) * 2;
        int bh_ = row * 64 + (( g      ^ (row & 7)) << 2) + wo;
        int bl_ = row * 64 + (((g + 8) ^ (row & 7)) << 2) + wo;
        *(uint2*)&As[bh_] = make_uint2(hw0, hw1);
        *(uint2*)&As[bl_] = make_uint2(lw0, lw1);
    }

    auto loadB = [&](int nb, unsigned* buf) {
#pragma unroll
        for (int j = 0; j < 4; j++) {
            int f = tid + 256 * j;
            int row = f >> 4, g = f & 15;
            cp16(buf + row * 64 + ((g ^ (row & 7)) << 2),
                 g_WuP + (size_t)(nb * 64 + row) * 64 + g * 4);
        }
    };
    loadB(0, Br[0]);
    CP_COMMIT();
    __syncthreads();

    /* A fragments -> registers, once */
    unsigned Ah[4][2][4], Al[4][2][4];
#pragma unroll
    for (int kk = 0; kk < 4; kk++) {
        const int p0 = ((kk * 2)     ^ r4) << 2;
        const int p1 = ((kk * 2 + 1) ^ r4) << 2;
#pragma unroll
        for (int mt = 0; mt < 2; mt++) {
            int ar0 = (wm * 32 + mt * 16 + r4) * 64 + c4;
            int ar1 = ar0 + 8 * 64;
            Ah[kk][mt][0] = As[ar0 + p0];
            Ah[kk][mt][1] = As[ar1 + p0];
            Ah[kk][mt][2] = As[ar0 + p1];
            Ah[kk][mt][3] = As[ar1 + p1];
            Al[kk][mt][0] = As[ar0 + p0 + 32];
            Al[kk][mt][1] = As[ar1 + p0 + 32];
            Al[kk][mt][2] = As[ar0 + p1 + 32];
            Al[kk][mt][3] = As[ar1 + p1 + 32];
        }
    }

    int bbi[2];
#pragma unroll
    for (int nt = 0; nt < 2; nt++)
        bbi[nt] = (wn * 16 + nt * 8 + r4) * 64 + c4;

    for (int nb = 0; nb < 12; nb++) {
        if (nb < 11) {
            loadB(nb + 1, Br[(nb + 1) & 1]);
            CP_COMMIT();
            CP_WAIT1();
        } else {
            CP_WAIT0();
        }
        __syncthreads();
        const unsigned* Bc = Br[nb & 1];

        float acc[2][2][4];
#pragma unroll
        for (int mt = 0; mt < 2; mt++)
#pragma unroll
            for (int nt = 0; nt < 2; nt++)
#pragma unroll
                for (int i = 0; i < 4; i++) acc[mt][nt][i] = 0.0f;

#pragma unroll
        for (int kk = 0; kk < 4; kk++) {
            const int p0 = ((kk * 2)     ^ r4) << 2;
            const int p1 = ((kk * 2 + 1) ^ r4) << 2;
            unsigned bh[2][2], bl[2][2];
#pragma unroll
            for (int nt = 0; nt < 2; nt++) {
                bh[nt][0] = Bc[bbi[nt] + p0];
                bh[nt][1] = Bc[bbi[nt] + p1];
                bl[nt][0] = Bc[bbi[nt] + p0 + 32];
                bl[nt][1] = Bc[bbi[nt] + p1 + 32];
            }
#pragma unroll
            for (int mt = 0; mt < 2; mt++)
#pragma unroll
                for (int nt = 0; nt < 2; nt++) {
                    MMA_BF16(acc[mt][nt], Al[kk][mt], bh[nt]);
                    MMA_BF16(acc[mt][nt], Ah[kk][mt], bl[nt]);
                    MMA_BF16(acc[mt][nt], Ah[kk][mt], bh[nt]);
                }
        }

        /* epilogue for this n-block: store out (gamma pre-folded) */
        int n0 = nb * 64;
#pragma unroll
        for (int mt = 0; mt < 2; mt++) {
            int row0 = m0 + wm * 32 + mt * 16 + r4;
#pragma unroll
            for (int nt = 0; nt < 2; nt++) {
                int col = n0 + wn * 16 + nt * 8 + 2 * c4;
                float2 o0, o1;
                o0.x = acc[mt][nt][0];
                o0.y = acc[mt][nt][1];
                o1.x = acc[mt][nt][2];
                o1.y = acc[mt][nt][3];
                *(float2*)(out + (size_t)row0 * D_DIM + col)       = o0;
                *(float2*)(out + (size_t)(row0 + 8) * D_DIM + col) = o1;
            }
        }
        __syncthreads();
    }
}

/* ------------------------------------------------------------------ */
extern "C" void kernel_launch(void* const* d_in, const int* in_sizes, int n_in,
                              void* d_out, int out_size) {
    const float* x     = (const float*)d_in[0];
    const float* Wd    = (const float*)d_in[1];
    const float* Wg    = (const float*)d_in[2];
    const float* We    = (const float*)d_in[3];
    const float* be    = (const float*)d_in[4];
    const float* Wu    = (const float*)d_in[5];
    const float* gamma = (const float*)d_in[6];
    float* out = (float*)d_out;

    k0_prep<<<88, 256>>>(We, Wu, gamma);
    k1_fused<<<(M_ROWS + 127) / 128, 256>>>(x, Wd, Wg, be);
    k3_gemm_out<<<M_ROWS / 64, 256>>>(out);
}

// round 15
// speedup vs baseline: 1.3129x; 1.3129x over previous
#include <cuda_runtime.h>
#include <cuda_bf16.h>
#include <math.h>
#include <cstdint>

#define D_DIM   768
#define R_DIM   64
#define E_NUM   4
#define NT      1029
#define BATCH   64
#define M_ROWS  (BATCH * NT)        /* 65856 = 64*1029 */

/* scratch: "full" buffer, transposed expert weights, pre-split packed Wu */
__device__ float    g_h[(size_t)M_ROWS * R_DIM];
__device__ float    g_WeT[E_NUM * R_DIM * R_DIM];
__device__ unsigned g_WuP[D_DIM * 64];   /* [d][64w]: hi words 0-31, lo 32-63 */

__device__ __forceinline__ float gelu_exact(float v) {
    return 0.5f * v * (1.0f + erff(v * 0.70710678118654752f));
}

/* bf16 split+pack via packed cvt: two floats -> hi word + lo (residual) word. */
__device__ __forceinline__ void bfsplit2(float f0, float f1,
                                         unsigned& hw, unsigned& lw) {
    asm("cvt.rn.satfinite.bf16x2.f32 %0, %1, %2;" : "=r"(hw) : "f"(f1), "f"(f0));
    float h0 = __uint_as_float(hw << 16);
    float h1 = __uint_as_float(hw & 0xFFFF0000u);
    float r0 = f0 - h0;
    float r1 = f1 - h1;
    asm("cvt.rn.satfinite.bf16x2.f32 %0, %1, %2;" : "=r"(lw) : "f"(r1), "f"(r0));
}

#define MMA_BF16(C, A, B)                                                     \
    asm volatile(                                                             \
        "mma.sync.aligned.m16n8k16.row.col.f32.bf16.bf16.f32 "                \
        "{%0,%1,%2,%3}, {%4,%5,%6,%7}, {%8,%9}, {%0,%1,%2,%3};"               \
        : "+f"((C)[0]), "+f"((C)[1]), "+f"((C)[2]), "+f"((C)[3])              \
        : "r"((A)[0]), "r"((A)[1]), "r"((A)[2]), "r"((A)[3]),                 \
          "r"((B)[0]), "r"((B)[1]))

__device__ __forceinline__ void cp16(void* smem, const void* g) {
    unsigned sa = (unsigned)__cvta_generic_to_shared(smem);
    asm volatile("cp.async.ca.shared.global [%0], [%1], 16;" :: "r"(sa), "l"(g));
}
#define CP_COMMIT() asm volatile("cp.async.commit_group;")
#define CP_WAIT1()  asm volatile("cp.async.wait_group 1;")
#define CP_WAIT0()  asm volatile("cp.async.wait_group 0;")

/* ------------------------------------------------------------------ */
/* K0 merged prep:                                                     */
/*  part 1 (i < 16384): WeT[e][r][s] = We[e][s][r]                     */
/*  part 2: Wu[d][64]*gamma[d] fp32 -> g_WuP[d][64w] packed bf16 hi/lo */
__global__ void k0_prep(const float* __restrict__ We,
                        const float* __restrict__ Wu,
                        const float* __restrict__ gamma) {
    int i = blockIdx.x * 256 + threadIdx.x;
    if (i < E_NUM * R_DIM * R_DIM) {
        int e = i >> 12;
        int r = (i >> 6) & 63;
        int s = i & 63;
        g_WeT[i] = We[(e << 12) + (s << 6) + r];
    }
    int j = i - E_NUM * R_DIM * R_DIM;
    if (j >= 0 && j < D_DIM * 8) {
        int d = j >> 3;
        int g = j & 7;
        float gm = gamma[d];
        const float* src = Wu + d * 64 + g * 8;
        float4 v0 = *(const float4*)(src);
        float4 v1 = *(const float4*)(src + 4);
        unsigned h0,l0,h1,l1,h2,l2,h3,l3;
        bfsplit2(v0.x * gm, v0.y * gm, h0, l0);
        bfsplit2(v0.z * gm, v0.w * gm, h1, l1);
        bfsplit2(v1.x * gm, v1.y * gm, h2, l2);
        bfsplit2(v1.z * gm, v1.w * gm, h3, l3);
        unsigned* dst = g_WuP + d * 64;
        *(uint4*)(dst + g * 4)      = make_uint4(h0, h1, h2, h3);
        *(uint4*)(dst + 32 + g * 4) = make_uint4(l0, l1, l2, l3);
    }
}

/* ------------------------------------------------------------------ */
/* K1 fused (3-term bf16): h = gelu(X.Wd^T) + top-1 MoE -> g_h.        */
/* 128(M)x64(N), K-step 32. Depth-1 LDG prefetch, fast packed convert. */
/* occupancy 2 CTAs/SM (full 128-reg budget -- 3 forces mainloop spill)*/
#define HS 66
__global__ __launch_bounds__(256, 2) void k1_fused(
    const float* __restrict__ X, const float* __restrict__ Wd,
    const float* __restrict__ Wg, const float* __restrict__ be)
{
    __shared__ __align__(16) unsigned s_buf[12288];  /* 48 KB */
    unsigned* Xp0 = s_buf;            /* 128 rows x 32 words */
    unsigned* Xp1 = s_buf + 4096;
    unsigned* Wp0 = s_buf + 8192;     /* 64 rows x 32 words  */
    unsigned* Wp1 = s_buf + 10240;
    float*    Hs  = (float*)s_buf;    /* reuse post-GEMM: 128*66 */

    const int tid  = threadIdx.x;
    const int wid  = tid >> 5;
    const int lane = tid & 31;
    const int wm   = wid >> 1;
    const int wn   = wid & 1;
    const int r4   = lane >> 2;
    const int c4   = lane & 3;
    const int m0   = blockIdx.x * 128;

    /* LDG assignments */
    int xrow[4], xkq[4];
    const float* xptr[4];
#pragma unroll
    for (int j = 0; j < 4; j++) {
        int f = tid + 256 * j;
        xrow[j] = f >> 3; xkq[j] = f & 7;
        int gr = m0 + xrow[j]; if (gr >= M_ROWS) gr = M_ROWS - 1;
        xptr[j] = X + (size_t)gr * D_DIM + xkq[j] * 4;
    }
    int wrow[2], wkq[2];
    const float* wptr[2];
#pragma unroll
    for (int j = 0; j < 2; j++) {
        int f = tid + 256 * j;
        wrow[j] = f >> 3; wkq[j] = f & 7;
        wptr[j] = Wd + wrow[j] * D_DIM + wkq[j] * 4;
    }

    /* fragment base indices */
    int arow[4], bbi[4];
#pragma unroll
    for (int i = 0; i < 4; i++)
        arow[i] = (wm * 32 + r4 + i * 8) * 32 + c4;
#pragma unroll
    for (int nt = 0; nt < 4; nt++)
        bbi[nt] = (wn * 32 + nt * 8 + r4) * 32 + c4;

    float acc[2][4][4];
#pragma unroll
    for (int mt = 0; mt < 2; mt++)
#pragma unroll
        for (int nt = 0; nt < 4; nt++)
#pragma unroll
            for (int i = 0; i < 4; i++) acc[mt][nt][i] = 0.0f;

    float4 xv[4], wv[2];
#pragma unroll
    for (int j = 0; j < 4; j++) xv[j] = *(const float4*)(xptr[j]);
#pragma unroll
    for (int j = 0; j < 2; j++) wv[j] = *(const float4*)(wptr[j]);

    for (int it = 0; it < 24; it++) {
        unsigned* Xp = (it & 1) ? Xp1 : Xp0;
        unsigned* Wp = (it & 1) ? Wp1 : Wp0;

        /* convert + packed store (hi granules 0-3, lo granules 4-7) */
#pragma unroll
        for (int j = 0; j < 4; j++) {
            unsigned hw0, lw0, hw1, lw1;
            bfsplit2(xv[j].x, xv[j].y, hw0, lw0);
            bfsplit2(xv[j].z, xv[j].w, hw1, lw1);
            int row = xrow[j], kq = xkq[j];
            int g   = kq >> 1;
            int wo  = (kq & 1) * 2;
            int bh_ = row * 32 + (( g      ^ (row & 7)) << 2) + wo;
            int bl_ = row * 32 + (((g + 4) ^ (row & 7)) << 2) + wo;
            *(uint2*)&Xp[bh_] = make_uint2(hw0, hw1);
            *(uint2*)&Xp[bl_] = make_uint2(lw0, lw1);
        }
#pragma unroll
        for (int j = 0; j < 2; j++) {
            unsigned hw0, lw0, hw1, lw1;
            bfsplit2(wv[j].x, wv[j].y, hw0, lw0);
            bfsplit2(wv[j].z, wv[j].w, hw1, lw1);
            int row = wrow[j], kq = wkq[j];
            int g   = kq >> 1;
            int wo  = (kq & 1) * 2;
            int bh_ = row * 32 + (( g      ^ (row & 7)) << 2) + wo;
            int bl_ = row * 32 + (((g + 4) ^ (row & 7)) << 2) + wo;
            *(uint2*)&Wp[bh_] = make_uint2(hw0, hw1);
            *(uint2*)&Wp[bl_] = make_uint2(lw0, lw1);
        }

        /* prefetch next k-tile into registers */
        if (it < 23) {
            int kt = (it + 1) * 32;
#pragma unroll
            for (int j = 0; j < 4; j++) xv[j] = *(const float4*)(xptr[j] + kt);
#pragma unroll
            for (int j = 0; j < 2; j++) wv[j] = *(const float4*)(wptr[j] + kt);
        }
        __syncthreads();

#pragma unroll
        for (int kk = 0; kk < 2; kk++) {
            const int p0  = ((kk * 2)     ^ r4) << 2;
            const int p1  = ((kk * 2 + 1) ^ r4) << 2;
            const int q0  = ((kk * 2 + 4) ^ r4) << 2;
            const int q1  = ((kk * 2 + 5) ^ r4) << 2;
            unsigned ah[2][4], al[2][4], bh[4][2], bl[4][2];
#pragma unroll
            for (int mt = 0; mt < 2; mt++) {
                ah[mt][0] = Xp[arow[2*mt]   + p0];
                ah[mt][1] = Xp[arow[2*mt+1] + p0];
                ah[mt][2] = Xp[arow[2*mt]   + p1];
                ah[mt][3] = Xp[arow[2*mt+1] + p1];
                al[mt][0] = Xp[arow[2*mt]   + q0];
                al[mt][1] = Xp[arow[2*mt+1] + q0];
                al[mt][2] = Xp[arow[2*mt]   + q1];
                al[mt][3] = Xp[arow[2*mt+1] + q1];
            }
#pragma unroll
            for (int nt = 0; nt < 4; nt++) {
                bh[nt][0] = Wp[bbi[nt] + p0];
                bh[nt][1] = Wp[bbi[nt] + p1];
                bl[nt][0] = Wp[bbi[nt] + q0];
                bl[nt][1] = Wp[bbi[nt] + q1];
            }
#pragma unroll
            for (int mt = 0; mt < 2; mt++)
#pragma unroll
                for (int nt = 0; nt < 4; nt++) {
                    MMA_BF16(acc[mt][nt], al[mt], bh[nt]);
                    MMA_BF16(acc[mt][nt], ah[mt], bl[nt]);
                    MMA_BF16(acc[mt][nt], ah[mt], bh[nt]);
                }
        }
    }
    __syncthreads();   /* all MMA reads done before s_buf reuse as Hs */

    /* ---- epilogue phase 1: gelu -> Hs (smem), stride 66 ---- */
#pragma unroll
    for (int mt = 0; mt < 2; mt++) {
        int lr = wm * 32 + mt * 16 + r4;
#pragma unroll
        for (int nt = 0; nt < 4; nt++) {
            int col = wn * 32 + nt * 8 + 2 * c4;
            Hs[lr * HS + col]           = gelu_exact(acc[mt][nt][0]);
            Hs[lr * HS + col + 1]       = gelu_exact(acc[mt][nt][1]);
            Hs[(lr + 8) * HS + col]     = gelu_exact(acc[mt][nt][2]);
            Hs[(lr + 8) * HS + col + 1] = gelu_exact(acc[mt][nt][3]);
        }
    }
    __syncthreads();

    /* ---- epilogue phase 2: per-token MoE, write final to g_h ---- */
    for (int grp = 0; grp < 4; grp++) {
        const int tb = wid * 16 + grp * 4;

        int   esel[4];
        float wsel[4];
        int   grow[4];
        int   vmoe[4];
#pragma unroll
        for (int j = 0; j < 4; j++) {
            int t = tb + j;
            int gr = m0 + t;
            grow[j] = gr;
            if (gr >= M_ROWS) { vmoe[j] = 0; }
            else {
                int bidx = gr / NT;
                int nidx = gr - bidx * NT;
                vmoe[j] = (nidx >= 5) ? 2 : 1;
            }
            float h0 = Hs[t * HS + lane];
            float h1 = Hs[t * HS + 32 + lane];
            float l0 = h0 * __ldg(Wg + lane)       + h1 * __ldg(Wg + 32 + lane);
            float l1 = h0 * __ldg(Wg + 64 + lane)  + h1 * __ldg(Wg + 96 + lane);
            float l2 = h0 * __ldg(Wg + 128 + lane) + h1 * __ldg(Wg + 160 + lane);
            float l3 = h0 * __ldg(Wg + 192 + lane) + h1 * __ldg(Wg + 224 + lane);
#pragma unroll
            for (int o = 16; o > 0; o >>= 1) {
                l0 += __shfl_xor_sync(0xffffffffu, l0, o);
                l1 += __shfl_xor_sync(0xffffffffu, l1, o);
                l2 += __shfl_xor_sync(0xffffffffu, l2, o);
                l3 += __shfl_xor_sync(0xffffffffu, l3, o);
            }
            float mx = fmaxf(fmaxf(l0, l1), fmaxf(l2, l3));
            float e0 = __expf(l0 - mx);
            float e1 = __expf(l1 - mx);
            float e2 = __expf(l2 - mx);
            float e3 = __expf(l3 - mx);
            float ssum = e0 + e1 + e2 + e3;
            int am = 0; float bv = l0; float ev = e0;
            if (l1 > bv) { bv = l1; am = 1; ev = e1; }
            if (l2 > bv) { bv = l2; am = 2; ev = e2; }
            if (l3 > bv) { bv = l3; am = 3; ev = e3; }
            esel[j] = am;
            wsel[j] = ev / ssum;
        }

        float acc2[4][2];
#pragma unroll
        for (int j = 0; j < 4; j++) { acc2[j][0] = 0.0f; acc2[j][1] = 0.0f; }
        const float* wp[4];
#pragma unroll
        for (int j = 0; j < 4; j++) wp[j] = g_WeT + (esel[j] << 12);

#pragma unroll 8
        for (int r = 0; r < 64; r++) {
#pragma unroll
            for (int j = 0; j < 4; j++) {
                float hr = Hs[(tb + j) * HS + r];
                float2 wv2 = *(const float2*)(wp[j] + (r << 6) + lane * 2);
                acc2[j][0] = fmaf(hr, wv2.x, acc2[j][0]);
                acc2[j][1] = fmaf(hr, wv2.y, acc2[j][1]);
            }
        }

#pragma unroll
        for (int j = 0; j < 4; j++) {
            if (vmoe[j] == 0) continue;
            int t = tb + j;
            int e = esel[j];
            float s = (vmoe[j] == 2) ? wsel[j] : 0.0f;
            float b0 = __ldg(be + (e << 6) + lane * 2);
            float b1 = __ldg(be + (e << 6) + lane * 2 + 1);
            float2 hv;
            hv.x = Hs[t * HS + lane * 2];
            hv.y = Hs[t * HS + lane * 2 + 1];
            float2 o;
            o.x = hv.x + s * (acc2[j][0] + b0);
            o.y = hv.y + s * (acc2[j][1] + b1);
            *(float2*)(g_h + (size_t)grow[j] * R_DIM + lane * 2) = o;
        }
    }
}

/* ------------------------------------------------------------------ */
/* K3 (3-term bf16): out = full . (Wu*gamma)^T   (gamma pre-folded)    */
/* M-tile 64. 8 warps 2m x 4n. A fragments register-resident.          */
__global__ __launch_bounds__(256, 2) void k3_gemm_out(float* __restrict__ out)
{
    __shared__ __align__(16) unsigned As[64 * 64];      /* 16 KB */
    __shared__ __align__(16) unsigned Br[2][64 * 64];   /* 2x16 KB */

    const int tid  = threadIdx.x;
    const int wid  = tid >> 5;
    const int lane = tid & 31;
    const int wm   = wid >> 2;          /* 0..1 */
    const int wn   = wid & 3;           /* 0..3 */
    const int r4   = lane >> 2;
    const int c4   = lane & 3;
    const int m0   = blockIdx.x * 64;

    /* A pack: 64 rows x 64 k fp32 -> packed bf16 hi(w0-31)/lo(w32-63) */
#pragma unroll
    for (int j = 0; j < 4; j++) {
        int f = tid + 256 * j;
        int row = f >> 4, kq = f & 15;
        float4 v = *(const float4*)(g_h + (size_t)(m0 + row) * R_DIM + kq * 4);
        unsigned hw0, lw0, hw1, lw1;
        bfsplit2(v.x, v.y, hw0, lw0);
        bfsplit2(v.z, v.w, hw1, lw1);
        int g  = kq >> 1;
        int wo = (kq & 1) * 2;
        int bh_ = row * 64 + (( g      ^ (row & 7)) << 2) + wo;
        int bl_ = row * 64 + (((g + 8) ^ (row & 7)) << 2) + wo;
        *(uint2*)&As[bh_] = make_uint2(hw0, hw1);
        *(uint2*)&As[bl_] = make_uint2(lw0, lw1);
    }

    auto loadB = [&](int nb, unsigned* buf) {
#pragma unroll
        for (int j = 0; j < 4; j++) {
            int f = tid + 256 * j;
            int row = f >> 4, g = f & 15;
            cp16(buf + row * 64 + ((g ^ (row & 7)) << 2),
                 g_WuP + (size_t)(nb * 64 + row) * 64 + g * 4);
        }
    };
    loadB(0, Br[0]);
    CP_COMMIT();
    __syncthreads();

    /* A fragments -> registers, once */
    unsigned Ah[4][2][4], Al[4][2][4];
#pragma unroll
    for (int kk = 0; kk < 4; kk++) {
        const int p0 = ((kk * 2)     ^ r4) << 2;
        const int p1 = ((kk * 2 + 1) ^ r4) << 2;
#pragma unroll
        for (int mt = 0; mt < 2; mt++) {
            int ar0 = (wm * 32 + mt * 16 + r4) * 64 + c4;
            int ar1 = ar0 + 8 * 64;
            Ah[kk][mt][0] = As[ar0 + p0];
            Ah[kk][mt][1] = As[ar1 + p0];
            Ah[kk][mt][2] = As[ar0 + p1];
            Ah[kk][mt][3] = As[ar1 + p1];
            Al[kk][mt][0] = As[ar0 + p0 + 32];
            Al[kk][mt][1] = As[ar1 + p0 + 32];
            Al[kk][mt][2] = As[ar0 + p1 + 32];
            Al[kk][mt][3] = As[ar1 + p1 + 32];
        }
    }

    int bbi[2];
#pragma unroll
    for (int nt = 0; nt < 2; nt++)
        bbi[nt] = (wn * 16 + nt * 8 + r4) * 64 + c4;

    for (int nb = 0; nb < 12; nb++) {
        if (nb < 11) {
            loadB(nb + 1, Br[(nb + 1) & 1]);
            CP_COMMIT();
            CP_WAIT1();
        } else {
            CP_WAIT0();
        }
        __syncthreads();
        const unsigned* Bc = Br[nb & 1];

        float acc[2][2][4];
#pragma unroll
        for (int mt = 0; mt < 2; mt++)
#pragma unroll
            for (int nt = 0; nt < 2; nt++)
#pragma unroll
                for (int i = 0; i < 4; i++) acc[mt][nt][i] = 0.0f;

#pragma unroll
        for (int kk = 0; kk < 4; kk++) {
            const int p0 = ((kk * 2)     ^ r4) << 2;
            const int p1 = ((kk * 2 + 1) ^ r4) << 2;
            unsigned bh[2][2], bl[2][2];
#pragma unroll
            for (int nt = 0; nt < 2; nt++) {
                bh[nt][0] = Bc[bbi[nt] + p0];
                bh[nt][1] = Bc[bbi[nt] + p1];
                bl[nt][0] = Bc[bbi[nt] + p0 + 32];
                bl[nt][1] = Bc[bbi[nt] + p1 + 32];
            }
#pragma unroll
            for (int mt = 0; mt < 2; mt++)
#pragma unroll
                for (int nt = 0; nt < 2; nt++) {
                    MMA_BF16(acc[mt][nt], Al[kk][mt], bh[nt]);
                    MMA_BF16(acc[mt][nt], Ah[kk][mt], bl[nt]);
                    MMA_BF16(acc[mt][nt], Ah[kk][mt], bh[nt]);
                }
        }

        /* epilogue for this n-block: store out (gamma pre-folded) */
        int n0 = nb * 64;
#pragma unroll
        for (int mt = 0; mt < 2; mt++) {
            int row0 = m0 + wm * 32 + mt * 16 + r4;
#pragma unroll
            for (int nt = 0; nt < 2; nt++) {
                int col = n0 + wn * 16 + nt * 8 + 2 * c4;
                float2 o0, o1;
                o0.x = acc[mt][nt][0];
                o0.y = acc[mt][nt][1];
                o1.x = acc[mt][nt][2];
                o1.y = acc[mt][nt][3];
                *(float2*)(out + (size_t)row0 * D_DIM + col)       = o0;
                *(float2*)(out + (size_t)(row0 + 8) * D_DIM + col) = o1;
            }
        }
        __syncthreads();
    }
}

/* ------------------------------------------------------------------ */
extern "C" void kernel_launch(void* const* d_in, const int* in_sizes, int n_in,
                              void* d_out, int out_size) {
    const float* x     = (const float*)d_in[0];
    const float* Wd    = (const float*)d_in[1];
    const float* Wg    = (const float*)d_in[2];
    const float* We    = (const float*)d_in[3];
    const float* be    = (const float*)d_in[4];
    const float* Wu    = (const float*)d_in[5];
    const float* gamma = (const float*)d_in[6];
    float* out = (float*)d_out;

    k0_prep<<<88, 256>>>(We, Wu, gamma);
    k1_fused<<<(M_ROWS + 127) / 128, 256>>>(x, Wd, Wg, be);
    k3_gemm_out<<<M_ROWS / 64, 256>>>(out);
}